// round 16
// baseline (speedup 1.0000x reference)
#include <cuda_runtime.h>
#include <cuda_fp16.h>

// Scratch: lgn transposed to channel-last [b][y][x][c] (4*64*64*64 f32 = 4MB)
__device__ float g_lgn_cl[4 * 64 * 64 * 64];
// Precomputed fp16 tables per batch: [b][0..511]=srh (folded Cy@Cr), [512..1023]=sxh (Cx)
__device__ uint4 g_tab[4][1024];

__device__ __forceinline__ float dot4(float4 a, float4 b) {
    return a.x * b.x + a.y * b.y + a.z * b.z + a.w * b.w;
}
__device__ __forceinline__ float4 rv(unsigned int a, unsigned int b) {
    const float2 lo = __half22float2(*(const __half2*)&a);
    const float2 hi = __half22float2(*(const __half2*)&b);
    return make_float4(lo.x, lo.y, hi.x, hi.y);
}
__device__ __forceinline__ unsigned int pk(float a, float b) {
    __half2 h = __floats2half2_rn(a, b);
    return *(unsigned int*)&h;
}
// broadcast one float into a half2 word (single cvt.rn.f16x2.f32)
__device__ __forceinline__ unsigned int h2bc(float w) {
    unsigned int r;
    asm("cvt.rn.f16x2.f32 %0, %1, %1;" : "=r"(r) : "f"(w));
    return r;
}
// fp16 corner blend: w0*a + w1*b per half lane (HMUL2 + HFMA2)
__device__ __forceinline__ unsigned int hblend(unsigned int a, unsigned int b,
                                               unsigned int w0, unsigned int w1) {
    const __half2 r = __hfma2(*(const __half2*)&w0, *(const __half2*)&a,
                              __hmul2(*(const __half2*)&w1, *(const __half2*)&b));
    return *(const unsigned int*)&r;
}

// ---------------------------------------------------------------------------
// Kernel 1 (fused prep): blocks 0..255 transpose lgn (B,C,H,W)->(B,H,W,C);
// blocks 256..259 build the fp16 coefficient tables (one block per batch).
// ---------------------------------------------------------------------------
__global__ __launch_bounds__(256) void prep_kernel(
    const float* __restrict__ lgn, const float* __restrict__ theta,
    const float* __restrict__ coefx, const float* __restrict__ coefy,
    const float* __restrict__ coefr)
{
    const int blk = blockIdx.x;
    const int t   = threadIdx.x;

    if (blk < 256) {
        __shared__ float tile[64][65];
        const int b = blk >> 6, y = blk & 63;
        const float* src = lgn + ((size_t)(b * 64) * 64 + y) * 64;  // + c*4096 + x

#pragma unroll
        for (int r = 0; r < 4; r++) {
            const int g  = r * 256 + t;
            const int c  = g >> 4;
            const int xq = g & 15;
            const float4 v = *(const float4*)(src + (size_t)c * 4096 + xq * 4);
            tile[c][xq * 4 + 0] = v.x;
            tile[c][xq * 4 + 1] = v.y;
            tile[c][xq * 4 + 2] = v.z;
            tile[c][xq * 4 + 3] = v.w;
        }
        __syncthreads();

        float* dst = g_lgn_cl + ((size_t)(b * 64) + y) * 4096;      // + x*64 + c
#pragma unroll
        for (int r = 0; r < 4; r++) {
            const int g  = r * 256 + t;
            const int x  = g >> 4;
            const int cq = g & 15;
            float4 v;
            v.x = tile[cq * 4 + 0][x];
            v.y = tile[cq * 4 + 1][x];
            v.z = tile[cq * 4 + 2][x];
            v.w = tile[cq * 4 + 3][x];
            *(float4*)(dst + (size_t)x * 64 + cq * 4) = v;
        }
    } else {
        const int b   = blk - 256;
        const int nv  = t & 15;
        const int row = t >> 4;
        const int hswz = (nv >> 2) & 1;
        const int nv2  = nv * 2;

        const float zc  = theta[b] / 3.14159265358979323846f;
        const float gz  = (zc + 1.0f) * 8.0f - 0.5f;
        const float z0f = floorf(gz);
        const int   z0  = (int)z0f;
        const float wz1 = gz - z0f;
        const float wz0e = (z0 >= 0 && z0 <= 15) ? (1.0f - wz1) : 0.0f;
        const float wz1e = (z0 + 1 >= 0 && z0 + 1 <= 15) ? wz1 : 0.0f;
        const int iz0 = min(max(z0, 0), 15);
        const int iz1 = min(max(z0 + 1, 0), 15);

        float Cyv[4][4];
#pragma unroll
        for (int k = 0; k < 4; k++)
#pragma unroll
            for (int j = 0; j < 4; j++) {
                const int base = ((nv * 4 + k) * 4 + j) * 16;
                Cyv[k][j] = wz0e * coefy[base + iz0] + wz1e * coefy[base + iz1];
            }

        float R[4][4];
#pragma unroll
        for (int k = 0; k < 4; k++)
#pragma unroll
            for (int l = 0; l < 4; l++) R[k][l] = 0.0f;
#pragma unroll
        for (int kp = 0; kp < 4; kp++)
#pragma unroll
            for (int l = 0; l < 4; l++) {
                const float s = coefr[((nv * 4 + kp) * 4 + l) * 16 + row];
#pragma unroll
                for (int k = 0; k < 4; k++) R[k][l] += Cyv[k][kp] * s;
            }

#pragma unroll
        for (int h = 0; h < 2; h++) {
            uint4 u;
            u.x = pk(R[2*h][0],   R[2*h][1]);
            u.y = pk(R[2*h][2],   R[2*h][3]);
            u.z = pk(R[2*h+1][0], R[2*h+1][1]);
            u.w = pk(R[2*h+1][2], R[2*h+1][3]);
            g_tab[b][row * 32 + nv2 + (h ^ hswz)] = u;

            float CA[4], CB[4];
#pragma unroll
            for (int l = 0; l < 4; l++) {
                CA[l] = coefx[((nv * 4 + 2*h)     * 4 + l) * 16 + row];
                CB[l] = coefx[((nv * 4 + 2*h + 1) * 4 + l) * 16 + row];
            }
            uint4 v;
            v.x = pk(CA[0], CA[1]); v.y = pk(CA[2], CA[3]);
            v.z = pk(CB[0], CB[1]); v.w = pk(CB[2], CB[3]);
            g_tab[b][512 + row * 32 + nv2 + (h ^ hswz)] = v;
        }
    }
}

// ---------------------------------------------------------------------------
// Kernel 2: main fused compute.
// Block = 256 threads = 16 pixels x 16 nv.
// Weight pass (threads 0..143): one (pixel,tap) record each —
//   wrec lo = {xw0, xw1, yw0(validity folded), yw1} fp16-broadcast words
//   wrec hi = {ix0*512|ix1*512<<16, iy0*512|iy1*512<<16, -, -}
//   wofs    = lgn float4 offset (separate array to keep row-hoist live set
//             at 3 u32 + 3 float4 instead of 3 full uint4 records)
// launch_bounds(256,6): 42 regs -> 6 blocks/SM = 888 concurrent, 1.15 waves.
// ---------------------------------------------------------------------------
__global__ __launch_bounds__(256, 6) void seprot_main_kernel(
    const float* __restrict__ grid1, const float* __restrict__ grid2,
    float* __restrict__ out)
{
    __shared__ uint4 tab[1024];        // srh = bytes [0,8192), sxh = [8192,16384)
    __shared__ uint4 wrec[16 * 9 * 2]; // per (pixel,tap): [lo, hi]
    __shared__ unsigned wofs[16 * 9];  // per (pixel,tap): lgn float4 offset
    __shared__ float so[64 * 17];      // output staging

    const int tid = threadIdx.x;
    const int b   = blockIdx.x >> 8;   // 256 blocks per batch

    // ---- table copy (all threads) ----
#pragma unroll
    for (int it = 0; it < 4; it++) {
        const int i = tid + it * 256;
        tab[i] = g_tab[b][i];
    }

    // ---- weight pass (threads 0..143: one (pixel, tap) each) ----
    if (tid < 144) {
        const int p  = tid / 9;
        const int k  = tid - p * 9;
        const int di = k / 3, dj = k - di * 3;     // 0..2

        const int P = blockIdx.x * 16 + p;
        const float2 g2 = ((const float2*)grid2)[P];
        const float fx = rintf((g2.x + 1.0f) * 32.0f - 0.5f);
        const float fy = rintf((g2.y + 1.0f) * 32.0f - 0.5f);
        const bool qv = (fx >= 0.0f) && (fx <= 63.0f) && (fy >= 0.0f) && (fy <= 63.0f);
        const int qx = (int)fx, qy = (int)fy;

        const int ty = qy + di - 1, tx = qx + dj - 1;
        const int tyc = min(max(ty, 0), 63), txc = min(max(tx, 0), 63);
        const float vm = (qv && (unsigned)ty < 64u && (unsigned)tx < 64u) ? 1.0f : 0.0f;

        const float2 g1 = ((const float2*)grid1)[b * 4096 + tyc * 64 + txc];
        const float dx = g2.x - g1.x;
        const float dy = g2.y - g1.y;

        const float gx  = (dx + 1.0f) * 8.0f - 0.5f;
        const float x0f = floorf(gx);
        const int   x0  = (int)x0f;
        const float wx1 = gx - x0f;
        const float wx0e = (x0 >= 0 && x0 <= 15) ? (1.0f - wx1) : 0.0f;
        const float wx1e = (x0 + 1 >= 0 && x0 + 1 <= 15) ? wx1 : 0.0f;
        const int ix0 = min(max(x0, 0), 15);
        const int ix1 = min(max(x0 + 1, 0), 15);

        const float gy  = (dy + 1.0f) * 8.0f - 0.5f;
        const float y0f = floorf(gy);
        const int   y0  = (int)y0f;
        const float wy1 = gy - y0f;
        const float wy0e = vm * ((y0 >= 0 && y0 <= 15) ? (1.0f - wy1) : 0.0f);
        const float wy1e = vm * ((y0 + 1 >= 0 && y0 + 1 <= 15) ? wy1 : 0.0f);
        const int iy0 = min(max(y0, 0), 15);
        const int iy1 = min(max(y0 + 1, 0), 15);

        uint4 lo, hi;
        lo.x = h2bc(wx0e); lo.y = h2bc(wx1e);
        lo.z = h2bc(wy0e); lo.w = h2bc(wy1e);
        hi.x = (unsigned)(ix0 * 512) | ((unsigned)(ix1 * 512) << 16);
        hi.y = (unsigned)(iy0 * 512) | ((unsigned)(iy1 * 512) << 16);
        hi.z = 0u; hi.w = 0u;
        wrec[(p * 9 + k) * 2 + 0] = lo;
        wrec[(p * 9 + k) * 2 + 1] = hi;
        wofs[p * 9 + k] = (unsigned)((tyc * 64 + txc) * 16);
    }
    __syncthreads();

    const int nv   = tid & 15;
    const int hswz = (nv >> 2) & 1;
    const int nv4  = nv * 4;
    const int nv2  = nv * 2;
    const int pl   = tid >> 4;                 // pixel within block, 0..15

    const int s0 = nv2 + (0 ^ hswz);
    const int s1 = nv2 + (1 ^ hswz);
    const char* ts0 = (const char*)tab + s0 * 16;   // srh row base for this nv
    const char* ts1 = (const char*)tab + s1 * 16;
    const char* ys0 = ts0 + 8192;                   // sxh
    const char* ys1 = ts1 + 8192;

    const float4* lbase = (const float4*)g_lgn_cl + (size_t)b * (4096 * 16) + nv;
    const int rbase = pl * 18;                 // uint4 index of this pixel's records
    const int obase9 = pl * 9;

    float acc0 = 0.0f, acc1 = 0.0f, acc2 = 0.0f, acc3 = 0.0f;

#pragma unroll
    for (int row = 0; row < 3; row++) {
        // hoist lgn offsets + gathers for the 3 taps of this row (MLP=3)
        const unsigned o0 = wofs[obase9 + row * 3 + 0];
        const unsigned o1 = wofs[obase9 + row * 3 + 1];
        const unsigned o2 = wofs[obase9 + row * 3 + 2];
        const float4 L0 = lbase[o0];
        const float4 L1 = lbase[o1];
        const float4 L2 = lbase[o2];

#pragma unroll
        for (int dj = 0; dj < 3; dj++) {
            const float4 L = (dj == 0) ? L0 : ((dj == 1) ? L1 : L2);
            const uint4 lo = wrec[rbase + (row * 3 + dj) * 2 + 0];
            const uint4 hh = wrec[rbase + (row * 3 + dj) * 2 + 1];

            const int ix0o = (int)(hh.x & 0xFFFFu), ix1o = (int)(hh.x >> 16);
            const int iy0o = (int)(hh.y & 0xFFFFu), iy1o = (int)(hh.y >> 16);

            // ---- x-stage: fp16 corner blend + fp32 dots with L ----
            const uint4 A0 = *(const uint4*)(ts0 + ix0o);
            const uint4 A1 = *(const uint4*)(ts1 + ix0o);
            const uint4 C0 = *(const uint4*)(ts0 + ix1o);
            const uint4 C1 = *(const uint4*)(ts1 + ix1o);

            uint4 B0, B1;
            B0.x = hblend(A0.x, C0.x, lo.x, lo.y);
            B0.y = hblend(A0.y, C0.y, lo.x, lo.y);
            B0.z = hblend(A0.z, C0.z, lo.x, lo.y);
            B0.w = hblend(A0.w, C0.w, lo.x, lo.y);
            B1.x = hblend(A1.x, C1.x, lo.x, lo.y);
            B1.y = hblend(A1.y, C1.y, lo.x, lo.y);
            B1.z = hblend(A1.z, C1.z, lo.x, lo.y);
            B1.w = hblend(A1.w, C1.w, lo.x, lo.y);

            const float u0 = dot4(rv(B0.x, B0.y), L);
            const float u1 = dot4(rv(B0.z, B0.w), L);
            const float u2 = dot4(rv(B1.x, B1.y), L);
            const float u3 = dot4(rv(B1.z, B1.w), L);
            const float4 u4 = make_float4(u0, u1, u2, u3);

            // ---- y-stage: fp16 corner blend (validity folded) + accumulate --
            const uint4 D0 = *(const uint4*)(ys0 + iy0o);
            const uint4 D1 = *(const uint4*)(ys1 + iy0o);
            const uint4 E0 = *(const uint4*)(ys0 + iy1o);
            const uint4 E1 = *(const uint4*)(ys1 + iy1o);

            uint4 F0, F1;
            F0.x = hblend(D0.x, E0.x, lo.z, lo.w);
            F0.y = hblend(D0.y, E0.y, lo.z, lo.w);
            F0.z = hblend(D0.z, E0.z, lo.z, lo.w);
            F0.w = hblend(D0.w, E0.w, lo.z, lo.w);
            F1.x = hblend(D1.x, E1.x, lo.z, lo.w);
            F1.y = hblend(D1.y, E1.y, lo.z, lo.w);
            F1.z = hblend(D1.z, E1.z, lo.z, lo.w);
            F1.w = hblend(D1.w, E1.w, lo.z, lo.w);

            acc0 += dot4(rv(F0.x, F0.y), u4);
            acc1 += dot4(rv(F0.z, F0.w), u4);
            acc2 += dot4(rv(F1.x, F1.y), u4);
            acc3 += dot4(rv(F1.z, F1.w), u4);
        }
    }

    // ---- stage outputs in smem, then coalesced stores ----
    so[(nv4 + 0) * 17 + pl] = acc0;
    so[(nv4 + 1) * 17 + pl] = acc1;
    so[(nv4 + 2) * 17 + pl] = acc2;
    so[(nv4 + 3) * 17 + pl] = acc3;
    __syncthreads();

    // out layout (B, 64, 64, 64): 16 consecutive pixels per block, same batch
    const int rem0 = (blockIdx.x & 255) * 16;
    float* obase = out + (size_t)b * 64 * 4096 + rem0;
#pragma unroll
    for (int i2 = 0; i2 < 4; i2++) {
        const int idx = tid + i2 * 256;
        const int c = idx >> 4, px = idx & 15;
        obase[(size_t)c * 4096 + px] = so[c * 17 + px];
    }
}

extern "C" void kernel_launch(void* const* d_in, const int* in_sizes, int n_in,
                              void* d_out, int out_size) {
    const float* grid1 = (const float*)d_in[0];
    const float* grid2 = (const float*)d_in[1];
    const float* theta = (const float*)d_in[2];
    const float* lgn   = (const float*)d_in[3];
    const float* coefx = (const float*)d_in[4];
    const float* coefy = (const float*)d_in[5];
    const float* coefr = (const float*)d_in[6];
    float* out = (float*)d_out;

    prep_kernel<<<260, 256>>>(lgn, theta, coefx, coefy, coefr);
    seprot_main_kernel<<<1024, 256>>>(grid1, grid2, out);
}

// round 17
// speedup vs baseline: 1.0808x; 1.0808x over previous
#include <cuda_runtime.h>
#include <cuda_fp16.h>

// Scratch: lgn transposed to channel-last [b][y][x][c] (4*64*64*64 f32 = 4MB)
__device__ float g_lgn_cl[4 * 64 * 64 * 64];
// Precomputed fp16 tables per batch: [b][0..511]=srh (folded Cy@Cr), [512..1023]=sxh (Cx)
__device__ uint4 g_tab[4][1024];

__device__ __forceinline__ float dot4(float4 a, float4 b) {
    return a.x * b.x + a.y * b.y + a.z * b.z + a.w * b.w;
}
__device__ __forceinline__ float4 rv(unsigned int a, unsigned int b) {
    const float2 lo = __half22float2(*(const __half2*)&a);
    const float2 hi = __half22float2(*(const __half2*)&b);
    return make_float4(lo.x, lo.y, hi.x, hi.y);
}
__device__ __forceinline__ unsigned int pk(float a, float b) {
    __half2 h = __floats2half2_rn(a, b);
    return *(unsigned int*)&h;
}
// broadcast one float into a half2 word (single cvt.rn.f16x2.f32)
__device__ __forceinline__ unsigned int h2bc(float w) {
    unsigned int r;
    asm("cvt.rn.f16x2.f32 %0, %1, %1;" : "=r"(r) : "f"(w));
    return r;
}
// fp16 corner blend: w0*a + w1*b per half lane (HMUL2 + HFMA2)
__device__ __forceinline__ unsigned int hblend(unsigned int a, unsigned int b,
                                               unsigned int w0, unsigned int w1) {
    const __half2 r = __hfma2(*(const __half2*)&w0, *(const __half2*)&a,
                              __hmul2(*(const __half2*)&w1, *(const __half2*)&b));
    return *(const unsigned int*)&r;
}

// ---------------------------------------------------------------------------
// Kernel 1 (fused prep): blocks 0..255 transpose lgn (B,C,H,W)->(B,H,W,C);
// blocks 256..259 build the fp16 coefficient tables (one block per batch).
// ---------------------------------------------------------------------------
__global__ __launch_bounds__(256) void prep_kernel(
    const float* __restrict__ lgn, const float* __restrict__ theta,
    const float* __restrict__ coefx, const float* __restrict__ coefy,
    const float* __restrict__ coefr)
{
    const int blk = blockIdx.x;
    const int t   = threadIdx.x;

    if (blk < 256) {
        __shared__ float tile[64][65];
        const int b = blk >> 6, y = blk & 63;
        const float* src = lgn + ((size_t)(b * 64) * 64 + y) * 64;  // + c*4096 + x

#pragma unroll
        for (int r = 0; r < 4; r++) {
            const int g  = r * 256 + t;
            const int c  = g >> 4;
            const int xq = g & 15;
            const float4 v = *(const float4*)(src + (size_t)c * 4096 + xq * 4);
            tile[c][xq * 4 + 0] = v.x;
            tile[c][xq * 4 + 1] = v.y;
            tile[c][xq * 4 + 2] = v.z;
            tile[c][xq * 4 + 3] = v.w;
        }
        __syncthreads();

        float* dst = g_lgn_cl + ((size_t)(b * 64) + y) * 4096;      // + x*64 + c
#pragma unroll
        for (int r = 0; r < 4; r++) {
            const int g  = r * 256 + t;
            const int x  = g >> 4;
            const int cq = g & 15;
            float4 v;
            v.x = tile[cq * 4 + 0][x];
            v.y = tile[cq * 4 + 1][x];
            v.z = tile[cq * 4 + 2][x];
            v.w = tile[cq * 4 + 3][x];
            *(float4*)(dst + (size_t)x * 64 + cq * 4) = v;
        }
    } else {
        const int b   = blk - 256;
        const int nv  = t & 15;
        const int row = t >> 4;
        const int hswz = (nv >> 2) & 1;
        const int nv2  = nv * 2;

        const float zc  = theta[b] / 3.14159265358979323846f;
        const float gz  = (zc + 1.0f) * 8.0f - 0.5f;
        const float z0f = floorf(gz);
        const int   z0  = (int)z0f;
        const float wz1 = gz - z0f;
        const float wz0e = (z0 >= 0 && z0 <= 15) ? (1.0f - wz1) : 0.0f;
        const float wz1e = (z0 + 1 >= 0 && z0 + 1 <= 15) ? wz1 : 0.0f;
        const int iz0 = min(max(z0, 0), 15);
        const int iz1 = min(max(z0 + 1, 0), 15);

        float Cyv[4][4];
#pragma unroll
        for (int k = 0; k < 4; k++)
#pragma unroll
            for (int j = 0; j < 4; j++) {
                const int base = ((nv * 4 + k) * 4 + j) * 16;
                Cyv[k][j] = wz0e * coefy[base + iz0] + wz1e * coefy[base + iz1];
            }

        float R[4][4];
#pragma unroll
        for (int k = 0; k < 4; k++)
#pragma unroll
            for (int l = 0; l < 4; l++) R[k][l] = 0.0f;
#pragma unroll
        for (int kp = 0; kp < 4; kp++)
#pragma unroll
            for (int l = 0; l < 4; l++) {
                const float s = coefr[((nv * 4 + kp) * 4 + l) * 16 + row];
#pragma unroll
                for (int k = 0; k < 4; k++) R[k][l] += Cyv[k][kp] * s;
            }

#pragma unroll
        for (int h = 0; h < 2; h++) {
            uint4 u;
            u.x = pk(R[2*h][0],   R[2*h][1]);
            u.y = pk(R[2*h][2],   R[2*h][3]);
            u.z = pk(R[2*h+1][0], R[2*h+1][1]);
            u.w = pk(R[2*h+1][2], R[2*h+1][3]);
            g_tab[b][row * 32 + nv2 + (h ^ hswz)] = u;

            float CA[4], CB[4];
#pragma unroll
            for (int l = 0; l < 4; l++) {
                CA[l] = coefx[((nv * 4 + 2*h)     * 4 + l) * 16 + row];
                CB[l] = coefx[((nv * 4 + 2*h + 1) * 4 + l) * 16 + row];
            }
            uint4 v;
            v.x = pk(CA[0], CA[1]); v.y = pk(CA[2], CA[3]);
            v.z = pk(CB[0], CB[1]); v.w = pk(CB[2], CB[3]);
            g_tab[b][512 + row * 32 + nv2 + (h ^ hswz)] = v;
        }
    }
}

// ---------------------------------------------------------------------------
// Kernel 2: main fused compute (R14 body; launch_bounds(256,4) -> 64-reg
// budget so ptxas can keep ~3 taps' LDS chains in flight).
// Block = 256 threads = 16 pixels x 16 nv.
// Weight pass: threads 0..143 compute one (pixel, tap) record each —
//   lo = {xw0, xw1, yw0(incl validity), yw1} as fp16-broadcast words
//   hi = {ix0*512|ix1*512<<16, iy0*512|iy1*512<<16, lgn float4-offset, 0}
// ---------------------------------------------------------------------------
__global__ __launch_bounds__(256, 4) void seprot_main_kernel(
    const float* __restrict__ grid1, const float* __restrict__ grid2,
    float* __restrict__ out)
{
    __shared__ uint4 tab[1024];        // srh = bytes [0,8192), sxh = [8192,16384)
    __shared__ uint4 wrec[16 * 9 * 2]; // per (pixel,tap): [lo, hi]
    __shared__ float so[64 * 17];      // output staging

    const int tid = threadIdx.x;
    const int b   = blockIdx.x >> 8;   // 256 blocks per batch

    // ---- table copy (all threads) ----
#pragma unroll
    for (int it = 0; it < 4; it++) {
        const int i = tid + it * 256;
        tab[i] = g_tab[b][i];
    }

    // ---- weight pass (threads 0..143: one (pixel, tap) each) ----
    if (tid < 144) {
        const int p  = tid / 9;
        const int k  = tid - p * 9;
        const int di = k / 3, dj = k - di * 3;     // 0..2

        const int P = blockIdx.x * 16 + p;
        const float2 g2 = ((const float2*)grid2)[P];
        const float fx = rintf((g2.x + 1.0f) * 32.0f - 0.5f);
        const float fy = rintf((g2.y + 1.0f) * 32.0f - 0.5f);
        const bool qv = (fx >= 0.0f) && (fx <= 63.0f) && (fy >= 0.0f) && (fy <= 63.0f);
        const int qx = (int)fx, qy = (int)fy;

        const int ty = qy + di - 1, tx = qx + dj - 1;
        const int tyc = min(max(ty, 0), 63), txc = min(max(tx, 0), 63);
        const float vm = (qv && (unsigned)ty < 64u && (unsigned)tx < 64u) ? 1.0f : 0.0f;

        const float2 g1 = ((const float2*)grid1)[b * 4096 + tyc * 64 + txc];
        const float dx = g2.x - g1.x;
        const float dy = g2.y - g1.y;

        const float gx  = (dx + 1.0f) * 8.0f - 0.5f;
        const float x0f = floorf(gx);
        const int   x0  = (int)x0f;
        const float wx1 = gx - x0f;
        const float wx0e = (x0 >= 0 && x0 <= 15) ? (1.0f - wx1) : 0.0f;
        const float wx1e = (x0 + 1 >= 0 && x0 + 1 <= 15) ? wx1 : 0.0f;
        const int ix0 = min(max(x0, 0), 15);
        const int ix1 = min(max(x0 + 1, 0), 15);

        const float gy  = (dy + 1.0f) * 8.0f - 0.5f;
        const float y0f = floorf(gy);
        const int   y0  = (int)y0f;
        const float wy1 = gy - y0f;
        const float wy0e = vm * ((y0 >= 0 && y0 <= 15) ? (1.0f - wy1) : 0.0f);
        const float wy1e = vm * ((y0 + 1 >= 0 && y0 + 1 <= 15) ? wy1 : 0.0f);
        const int iy0 = min(max(y0, 0), 15);
        const int iy1 = min(max(y0 + 1, 0), 15);

        uint4 lo, hi;
        lo.x = h2bc(wx0e); lo.y = h2bc(wx1e);
        lo.z = h2bc(wy0e); lo.w = h2bc(wy1e);
        hi.x = (unsigned)(ix0 * 512) | ((unsigned)(ix1 * 512) << 16);
        hi.y = (unsigned)(iy0 * 512) | ((unsigned)(iy1 * 512) << 16);
        hi.z = (unsigned)((tyc * 64 + txc) * 16);   // float4 offset into lgn slice
        hi.w = 0u;
        wrec[(p * 9 + k) * 2 + 0] = lo;
        wrec[(p * 9 + k) * 2 + 1] = hi;
    }
    __syncthreads();

    const int nv   = tid & 15;
    const int hswz = (nv >> 2) & 1;
    const int nv4  = nv * 4;
    const int nv2  = nv * 2;
    const int pl   = tid >> 4;                 // pixel within block, 0..15

    const int s0 = nv2 + (0 ^ hswz);
    const int s1 = nv2 + (1 ^ hswz);
    const char* ts0 = (const char*)tab + s0 * 16;   // srh row base for this nv
    const char* ts1 = (const char*)tab + s1 * 16;
    const char* ys0 = ts0 + 8192;                   // sxh
    const char* ys1 = ts1 + 8192;

    const float4* lbase = (const float4*)g_lgn_cl + (size_t)b * (4096 * 16) + nv;
    const int rbase = pl * 18;                 // uint4 index of this pixel's records

    float acc0 = 0.0f, acc1 = 0.0f, acc2 = 0.0f, acc3 = 0.0f;

#pragma unroll
    for (int row = 0; row < 3; row++) {
        // hoist hi-records + lgn gathers for the 3 taps of this row (MLP=3)
        const uint4 h0 = wrec[rbase + (row * 3 + 0) * 2 + 1];
        const uint4 h1 = wrec[rbase + (row * 3 + 1) * 2 + 1];
        const uint4 h2 = wrec[rbase + (row * 3 + 2) * 2 + 1];
        const float4 L0 = lbase[h0.z];
        const float4 L1 = lbase[h1.z];
        const float4 L2 = lbase[h2.z];

#pragma unroll
        for (int dj = 0; dj < 3; dj++) {
            const uint4 hh = (dj == 0) ? h0 : ((dj == 1) ? h1 : h2);
            const float4 L = (dj == 0) ? L0 : ((dj == 1) ? L1 : L2);
            const uint4 lo = wrec[rbase + (row * 3 + dj) * 2];

            const int ix0o = (int)(hh.x & 0xFFFFu), ix1o = (int)(hh.x >> 16);
            const int iy0o = (int)(hh.y & 0xFFFFu), iy1o = (int)(hh.y >> 16);

            // ---- x-stage: fp16 corner blend + fp32 dots with L ----
            const uint4 A0 = *(const uint4*)(ts0 + ix0o);
            const uint4 A1 = *(const uint4*)(ts1 + ix0o);
            const uint4 C0 = *(const uint4*)(ts0 + ix1o);
            const uint4 C1 = *(const uint4*)(ts1 + ix1o);

            uint4 B0, B1;
            B0.x = hblend(A0.x, C0.x, lo.x, lo.y);
            B0.y = hblend(A0.y, C0.y, lo.x, lo.y);
            B0.z = hblend(A0.z, C0.z, lo.x, lo.y);
            B0.w = hblend(A0.w, C0.w, lo.x, lo.y);
            B1.x = hblend(A1.x, C1.x, lo.x, lo.y);
            B1.y = hblend(A1.y, C1.y, lo.x, lo.y);
            B1.z = hblend(A1.z, C1.z, lo.x, lo.y);
            B1.w = hblend(A1.w, C1.w, lo.x, lo.y);

            const float u0 = dot4(rv(B0.x, B0.y), L);
            const float u1 = dot4(rv(B0.z, B0.w), L);
            const float u2 = dot4(rv(B1.x, B1.y), L);
            const float u3 = dot4(rv(B1.z, B1.w), L);
            const float4 u4 = make_float4(u0, u1, u2, u3);

            // ---- y-stage: fp16 corner blend (validity folded) + accumulate --
            const uint4 D0 = *(const uint4*)(ys0 + iy0o);
            const uint4 D1 = *(const uint4*)(ys1 + iy0o);
            const uint4 E0 = *(const uint4*)(ys0 + iy1o);
            const uint4 E1 = *(const uint4*)(ys1 + iy1o);

            uint4 F0, F1;
            F0.x = hblend(D0.x, E0.x, lo.z, lo.w);
            F0.y = hblend(D0.y, E0.y, lo.z, lo.w);
            F0.z = hblend(D0.z, E0.z, lo.z, lo.w);
            F0.w = hblend(D0.w, E0.w, lo.z, lo.w);
            F1.x = hblend(D1.x, E1.x, lo.z, lo.w);
            F1.y = hblend(D1.y, E1.y, lo.z, lo.w);
            F1.z = hblend(D1.z, E1.z, lo.z, lo.w);
            F1.w = hblend(D1.w, E1.w, lo.z, lo.w);

            acc0 += dot4(rv(F0.x, F0.y), u4);
            acc1 += dot4(rv(F0.z, F0.w), u4);
            acc2 += dot4(rv(F1.x, F1.y), u4);
            acc3 += dot4(rv(F1.z, F1.w), u4);
        }
    }

    // ---- stage outputs in smem, then coalesced stores ----
    so[(nv4 + 0) * 17 + pl] = acc0;
    so[(nv4 + 1) * 17 + pl] = acc1;
    so[(nv4 + 2) * 17 + pl] = acc2;
    so[(nv4 + 3) * 17 + pl] = acc3;
    __syncthreads();

    // out layout (B, 64, 64, 64): 16 consecutive pixels per block, same batch
    const int rem0 = (blockIdx.x & 255) * 16;
    float* obase = out + (size_t)b * 64 * 4096 + rem0;
#pragma unroll
    for (int i2 = 0; i2 < 4; i2++) {
        const int idx = tid + i2 * 256;
        const int c = idx >> 4, px = idx & 15;
        obase[(size_t)c * 4096 + px] = so[c * 17 + px];
    }
}

extern "C" void kernel_launch(void* const* d_in, const int* in_sizes, int n_in,
                              void* d_out, int out_size) {
    const float* grid1 = (const float*)d_in[0];
    const float* grid2 = (const float*)d_in[1];
    const float* theta = (const float*)d_in[2];
    const float* lgn   = (const float*)d_in[3];
    const float* coefx = (const float*)d_in[4];
    const float* coefy = (const float*)d_in[5];
    const float* coefr = (const float*)d_in[6];
    float* out = (float*)d_out;

    prep_kernel<<<260, 256>>>(lgn, theta, coefx, coefy, coefr);
    seprot_main_kernel<<<1024, 256>>>(grid1, grid2, out);
}